// round 7
// baseline (speedup 1.0000x reference)
#include <cuda_runtime.h>
#include <float.h>

// AttentionSelector (R7 = R6 + persistent ticket scheduler).
//  Work unit = group of 8 consecutive bags (contiguous row span).
//  Persistent CTAs (grid = 4*148) pull groups off a global atomic ticket:
//  removes wave quantization (5.28 waves) and span-size imbalance.
//  Per group:
//   P1: warps stride over span rows, 2 rows/iter -> logits to smem
//   P2: warp w softmax for bag w in smem
//   P3: warp w streams its bag rows (2/iter) -> att in regs, no reduces
//   P4: register-tiled micro-GEMM (7 rel rows x 8 bags per warp, split 4+3)
// scope/labels are int32 on device (JAX x64-disabled downgrades int64).

static constexpr int Dd  = 690;
static constexpr int F2  = 345;   // float2 per row
static constexpr int NCH = 11;    // ceil(345/32) float2-chunks per lane
static constexpr int RR  = 53;
static constexpr int NT  = 256;
static constexpr int NW  = 8;     // warps = bags per group
static constexpr int SP2 = 352;   // s_att2 row stride in float2
static constexpr int RPW = 7;     // rel rows per warp in P4
static constexpr int CAP = 512;   // max rows per group span (fallback below)
static constexpr int CTAS_PER_SM = 4;

__device__ int g_ticket;

__global__ void reset_ticket() { g_ticket = 0; }

__device__ __forceinline__ float wsum(float v) {
#pragma unroll
    for (int o = 16; o; o >>= 1) v += __shfl_xor_sync(0xffffffffu, v, o);
    return v;
}
__device__ __forceinline__ float wmax(float v) {
#pragma unroll
    for (int o = 16; o; o >>= 1) v = fmaxf(v, __shfl_xor_sync(0xffffffffu, v, o));
    return v;
}

__device__ __forceinline__ float dot_row(const float2* __restrict__ rp,
                                         const float2* __restrict__ lp,
                                         int lane) {
    float pa0 = 0.f, pa1 = 0.f;
#pragma unroll
    for (int c = 0; c < NCH; c++) {
        const int k = c * 32 + lane;
        if (k < F2) {
            const float2 x = rp[k], y = lp[k];
            if (c & 1) { pa1 = fmaf(x.x, y.x, pa1); pa1 = fmaf(x.y, y.y, pa1); }
            else       { pa0 = fmaf(x.x, y.x, pa0); pa0 = fmaf(x.y, y.y, pa0); }
        }
    }
    return pa0 + pa1;
}

__global__ __launch_bounds__(NT, CTAS_PER_SM) void bag_kernel(
    const float* __restrict__ repre,
    const float* __restrict__ rel,
    const float* __restrict__ bias,
    const int*   __restrict__ scope,
    const int*   __restrict__ labels,
    float* __restrict__ out,
    int num_groups)
{
    __shared__ float  s_log[CAP];
    __shared__ __align__(16) float2 s_att2[NW * SP2];  // 22.5 KB
    __shared__ int s_group;

    const int tid  = threadIdx.x;
    const int lane = tid & 31;
    const int wid  = tid >> 5;

    while (true) {
        if (tid == 0) s_group = atomicAdd(&g_ticket, 1);
        __syncthreads();
        const int grp = s_group;
        if (grp >= num_groups) break;
        __syncthreads();   // s_group safely consumed before next overwrite

        const int bag0 = grp * NW;
        const int bag  = bag0 + wid;
        const int start = scope[2 * bag];
        const int end   = scope[2 * bag + 1];
        const int row0  = scope[2 * bag0];
        const int row1  = scope[2 * (bag0 + NW - 1) + 1];

        if (row1 - row0 <= CAP) {
            // ---- P1: logits for span rows, warp-strided, 2 rows/iter ----
            int i = row0 + wid;
            for (; i + NW < row1; i += 2 * NW) {
                const int i2 = i + NW;
                const float2* rp0 = reinterpret_cast<const float2*>(repre + i  * Dd);
                const float2* lp0 = reinterpret_cast<const float2*>(rel + labels[i]  * Dd);
                const float2* rp1 = reinterpret_cast<const float2*>(repre + i2 * Dd);
                const float2* lp1 = reinterpret_cast<const float2*>(rel + labels[i2] * Dd);
                float a0 = 0.f, a1 = 0.f, b0 = 0.f, b1 = 0.f;
#pragma unroll
                for (int c = 0; c < NCH; c++) {
                    const int k = c * 32 + lane;
                    if (k < F2) {
                        const float2 x0 = rp0[k], y0 = lp0[k];
                        const float2 x1 = rp1[k], y1 = lp1[k];
                        if (c & 1) {
                            a1 = fmaf(x0.x, y0.x, a1); a1 = fmaf(x0.y, y0.y, a1);
                            b1 = fmaf(x1.x, y1.x, b1); b1 = fmaf(x1.y, y1.y, b1);
                        } else {
                            a0 = fmaf(x0.x, y0.x, a0); a0 = fmaf(x0.y, y0.y, a0);
                            b0 = fmaf(x1.x, y1.x, b0); b0 = fmaf(x1.y, y1.y, b0);
                        }
                    }
                }
                float accA = a0 + a1;
                float accB = b0 + b1;
#pragma unroll
                for (int o = 16; o; o >>= 1) {
                    accA += __shfl_xor_sync(0xffffffffu, accA, o);
                    accB += __shfl_xor_sync(0xffffffffu, accB, o);
                }
                if (lane == 0) { s_log[i - row0] = accA; s_log[i2 - row0] = accB; }
            }
            if (i < row1) {
                const float2* rp = reinterpret_cast<const float2*>(repre + i * Dd);
                const float2* lp = reinterpret_cast<const float2*>(rel + labels[i] * Dd);
                const float acc = wsum(dot_row(rp, lp, lane));
                if (lane == 0) s_log[i - row0] = acc;
            }
            __syncthreads();

            // ---- P2: softmax for own bag ----
            const int n   = end - start;
            const int off = start - row0;
            float tm = -FLT_MAX;
            for (int j = lane; j < n; j += 32) tm = fmaxf(tm, s_log[off + j]);
            tm = wmax(tm);
            float ps = 0.f;
            for (int j = lane; j < n; j += 32) {
                const float e = __expf(s_log[off + j] - tm);
                s_log[off + j] = e;
                ps += e;
            }
            ps = wsum(ps);
            const float inv = 1.0f / ps;
            __syncwarp();

            // ---- P3: weighted pool of own bag (2 rows/iter, no reduces) ----
            float2 att[NCH];
#pragma unroll
            for (int c = 0; c < NCH; c++) att[c] = make_float2(0.f, 0.f);
            int r = 0;
            for (; r + 2 <= n; r += 2) {
                const float w0 = s_log[off + r];
                const float w1 = s_log[off + r + 1];
                const float2* rp0 = reinterpret_cast<const float2*>(repre + (start + r)     * Dd);
                const float2* rp1 = reinterpret_cast<const float2*>(repre + (start + r + 1) * Dd);
#pragma unroll
                for (int c = 0; c < NCH; c++) {
                    const int k = c * 32 + lane;
                    if (k < F2) {
                        const float2 x0 = rp0[k], x1 = rp1[k];
                        att[c].x = fmaf(w0, x0.x, att[c].x);
                        att[c].y = fmaf(w0, x0.y, att[c].y);
                        att[c].x = fmaf(w1, x1.x, att[c].x);
                        att[c].y = fmaf(w1, x1.y, att[c].y);
                    }
                }
            }
            if (r < n) {
                const float w = s_log[off + r];
                const float2* rp = reinterpret_cast<const float2*>(repre + (start + r) * Dd);
#pragma unroll
                for (int c = 0; c < NCH; c++) {
                    const int k = c * 32 + lane;
                    if (k < F2) {
                        const float2 x = rp[k];
                        att[c].x = fmaf(w, x.x, att[c].x);
                        att[c].y = fmaf(w, x.y, att[c].y);
                    }
                }
            }
#pragma unroll
            for (int c = 0; c < NCH; c++) {
                const int k = c * 32 + lane;
                if (k < F2) s_att2[wid * SP2 + k] = make_float2(att[c].x * inv, att[c].y * inv);
            }
        } else {
            // ---- fallback for giant spans (block-uniform branch; correct) ----
            float tm = -FLT_MAX;
            for (int i = start; i < end; i++) {
                const float2* rp = reinterpret_cast<const float2*>(repre + i * Dd);
                const float2* lp = reinterpret_cast<const float2*>(rel + labels[i] * Dd);
                tm = fmaxf(tm, wsum(dot_row(rp, lp, lane)));
            }
            float2 att[NCH];
#pragma unroll
            for (int c = 0; c < NCH; c++) att[c] = make_float2(0.f, 0.f);
            float s = 0.f;
            for (int i = start; i < end; i++) {
                const float2* rp = reinterpret_cast<const float2*>(repre + i * Dd);
                const float2* lp = reinterpret_cast<const float2*>(rel + labels[i] * Dd);
                const float e = __expf(wsum(dot_row(rp, lp, lane)) - tm);
                s += e;
#pragma unroll
                for (int c = 0; c < NCH; c++) {
                    const int k = c * 32 + lane;
                    if (k < F2) {
                        const float2 x = rp[k];
                        att[c].x = fmaf(e, x.x, att[c].x);
                        att[c].y = fmaf(e, x.y, att[c].y);
                    }
                }
            }
            const float inv = 1.0f / s;
#pragma unroll
            for (int c = 0; c < NCH; c++) {
                const int k = c * 32 + lane;
                if (k < F2) s_att2[wid * SP2 + k] = make_float2(att[c].x * inv, att[c].y * inv);
            }
        }
        __syncthreads();

        // ---- P4: out[bag][r] = dot(att[bag], rel[r]) + bias[r] (7x8, 4+3) ----
        const int r0w = wid * RPW;
#pragma unroll
        for (int g = 0; g < 2; g++) {
            const int jb = g ? 4 : 0;
            const int jn = g ? 3 : 4;
            float acc4[4][NW];
#pragma unroll
            for (int j = 0; j < 4; j++)
#pragma unroll
                for (int b = 0; b < NW; b++) acc4[j][b] = 0.f;

            for (int c = 0; c < NCH; c++) {
                const int k = c * 32 + lane;
                const bool v = (k < F2);
                float2 a[NW];
#pragma unroll
                for (int b = 0; b < NW; b++)
                    a[b] = v ? s_att2[b * SP2 + k] : make_float2(0.f, 0.f);
#pragma unroll
                for (int j = 0; j < 4; j++) {
                    if (j >= jn) break;
                    const int rr = r0w + jb + j;
                    float2 rv = make_float2(0.f, 0.f);
                    if (v && rr < RR)
                        rv = reinterpret_cast<const float2*>(rel)[rr * F2 + k];
#pragma unroll
                    for (int b = 0; b < NW; b++) {
                        acc4[j][b] = fmaf(rv.x, a[b].x, acc4[j][b]);
                        acc4[j][b] = fmaf(rv.y, a[b].y, acc4[j][b]);
                    }
                }
            }
#pragma unroll
            for (int j = 0; j < 4; j++) {
                if (j >= jn) break;
                const int rr = r0w + jb + j;
#pragma unroll
                for (int b = 0; b < NW; b++) {
                    const float v = wsum(acc4[j][b]);
                    if (lane == 0 && rr < RR)
                        out[(bag0 + b) * RR + rr] = v + bias[rr];
                }
            }
        }
        __syncthreads();   // s_att2/s_log free for next group
    }
}

extern "C" void kernel_launch(void* const* d_in, const int* in_sizes, int n_in,
                              void* d_out, int out_size) {
    const float* repre  = (const float*)d_in[0];
    const float* rel    = (const float*)d_in[1];
    const float* bias   = (const float*)d_in[2];
    const int*   scope  = (const int*)d_in[3];
    const int*   labels = (const int*)d_in[4];
    float* out = (float*)d_out;

    const int num_bags   = in_sizes[3] / 2;   // 25000
    const int num_groups = num_bags / NW;     // 3125 (exact)

    reset_ticket<<<1, 1>>>();
    bag_kernel<<<148 * CTAS_PER_SM, NT>>>(repre, rel, bias, scope, labels, out,
                                          num_groups);
}